// round 3
// baseline (speedup 1.0000x reference)
#include <cuda_runtime.h>
#include <cstdint>

// out[dst[e], :] += w[e] * x[src[e], :]
// x: [N, 64] f32; edge_weight: [E] f32; edge_index: [2, E] int32; out: [N, 64] f32
//
// 4 threads per edge, 4 float4 chunks each (64B contiguous per thread,
// 256B contiguous per 4-lane group). Loads front-batched for MLP=4, then
// 4x red.global.add.v4.f32 (one 16B L2 atomic per chunk).

static constexpr int F = 64;
static constexpr int TPE = 4;              // threads per edge
static constexpr int CPT = 4;              // float4 chunks per thread
static constexpr int THREADS = 256;

__global__ void __launch_bounds__(THREADS)
mp_scatter_kernel(const float* __restrict__ x,
                  const float* __restrict__ ew,
                  const int* __restrict__ ei,   // [2, E] int32
                  float* __restrict__ out,
                  int E)
{
    int idx = blockIdx.x * THREADS + threadIdx.x;     // E*4 = 4M
    if (idx >= E * TPE) return;

    int e = idx >> 2;          // edge id
    int q = idx & 3;           // quarter of the row

    // Broadcast among the 4 lanes of this edge; streamed once -> evict-first.
    int   s = __ldcs(&ei[e]);
    int   d = __ldcs(&ei[E + e]);
    float w = __ldcs(&ew[e]);

    const float4* xs = reinterpret_cast<const float4*>(x + (long long)s * F + q * 16);
    // Front-batch 4 independent 16B loads (MLP=4).
    float4 v0 = __ldg(&xs[0]);
    float4 v1 = __ldg(&xs[1]);
    float4 v2 = __ldg(&xs[2]);
    float4 v3 = __ldg(&xs[3]);

    v0.x *= w; v0.y *= w; v0.z *= w; v0.w *= w;
    v1.x *= w; v1.y *= w; v1.z *= w; v1.w *= w;
    v2.x *= w; v2.y *= w; v2.z *= w; v2.w *= w;
    v3.x *= w; v3.y *= w; v3.z *= w; v3.w *= w;

    float* dp = out + (long long)d * F + q * 16;
    asm volatile("red.global.add.v4.f32 [%0], {%1, %2, %3, %4};"
                 :: "l"(dp +  0), "f"(v0.x), "f"(v0.y), "f"(v0.z), "f"(v0.w) : "memory");
    asm volatile("red.global.add.v4.f32 [%0], {%1, %2, %3, %4};"
                 :: "l"(dp +  4), "f"(v1.x), "f"(v1.y), "f"(v1.z), "f"(v1.w) : "memory");
    asm volatile("red.global.add.v4.f32 [%0], {%1, %2, %3, %4};"
                 :: "l"(dp +  8), "f"(v2.x), "f"(v2.y), "f"(v2.z), "f"(v2.w) : "memory");
    asm volatile("red.global.add.v4.f32 [%0], {%1, %2, %3, %4};"
                 :: "l"(dp + 12), "f"(v3.x), "f"(v3.y), "f"(v3.z), "f"(v3.w) : "memory");
}

extern "C" void kernel_launch(void* const* d_in, const int* in_sizes, int n_in,
                              void* d_out, int out_size)
{
    const float* x  = (const float*)d_in[0];
    const float* ew = (const float*)d_in[1];
    const int*   ei = (const int*)d_in[2];
    float* out = (float*)d_out;

    int E = in_sizes[2] / 2;             // edge_index holds 2*E elements

    cudaMemsetAsync(out, 0, (size_t)out_size * sizeof(float), 0);

    int total = E * TPE;
    int blocks = (total + THREADS - 1) / THREADS;
    mp_scatter_kernel<<<blocks, THREADS>>>(x, ew, ei, out, E);
}

// round 4
// speedup vs baseline: 1.5545x; 1.5545x over previous
#include <cuda_runtime.h>
#include <cstdint>

// out[dst[e], :] += w[e] * x[src[e], :]
// x: [N, 64] f32; edge_weight: [E] f32; edge_index: [2, E] int32; out: [N, 64] f32
//
// 16 lanes per edge, one float4 chunk per lane (fully coalesced 256B rows per
// LDG.128 warp-wide), 2 edges per thread for MLP=2 on the gather chain.
// Scatter via red.global.add.v4.f32 (one 16B L2 atomic per chunk).

static constexpr int F = 64;
static constexpr int THREADS = 256;

__global__ void __launch_bounds__(THREADS)
mp_scatter_kernel(const float* __restrict__ x,
                  const float* __restrict__ ew,
                  const int* __restrict__ ei,   // [2, E] int32
                  float* __restrict__ out,
                  int E)                        // E assumed even (E=1M)
{
    int idx = blockIdx.x * THREADS + threadIdx.x;   // one thread = chunk c of edge pair
    int pairs = E >> 1;
    int total = pairs * 16;                          // 8M
    if (idx >= total) return;

    int p = idx >> 4;           // edge pair id
    int c = idx & 15;           // chunk id within row
    int e0 = p * 2;             // even edge -> int2/float2 aligned

    // Vectorized, broadcast-within-16-lanes; streamed (no reuse) -> evict-first.
    int2   s2 = __ldcs(reinterpret_cast<const int2*>(ei + e0));
    int2   d2 = __ldcs(reinterpret_cast<const int2*>(ei + E + e0));
    float2 w2 = __ldcs(reinterpret_cast<const float2*>(ew + e0));

    // Two independent gather chains (front-batched -> MLP=2).
    float4 va = __ldg(reinterpret_cast<const float4*>(x + (long long)s2.x * F + c * 4));
    float4 vb = __ldg(reinterpret_cast<const float4*>(x + (long long)s2.y * F + c * 4));

    va.x *= w2.x; va.y *= w2.x; va.z *= w2.x; va.w *= w2.x;
    vb.x *= w2.y; vb.y *= w2.y; vb.z *= w2.y; vb.w *= w2.y;

    float* pa = out + (long long)d2.x * F + c * 4;
    float* pb = out + (long long)d2.y * F + c * 4;
    asm volatile("red.global.add.v4.f32 [%0], {%1, %2, %3, %4};"
                 :: "l"(pa), "f"(va.x), "f"(va.y), "f"(va.z), "f"(va.w) : "memory");
    asm volatile("red.global.add.v4.f32 [%0], {%1, %2, %3, %4};"
                 :: "l"(pb), "f"(vb.x), "f"(vb.y), "f"(vb.z), "f"(vb.w) : "memory");
}

__global__ void __launch_bounds__(THREADS)
mp_scatter_tail(const float* __restrict__ x,
                const float* __restrict__ ew,
                const int* __restrict__ ei,
                float* __restrict__ out,
                int E, int e_start)
{
    // Handles leftover odd edge if E is odd (not expected for E=1M; safety).
    int idx = blockIdx.x * THREADS + threadIdx.x;
    int n = (E - e_start) * 16;
    if (idx >= n) return;
    int e = e_start + (idx >> 4);
    int c = idx & 15;
    int   s = __ldg(&ei[e]);
    int   d = __ldg(&ei[E + e]);
    float w = __ldg(&ew[e]);
    float4 v = __ldg(reinterpret_cast<const float4*>(x + (long long)s * F + c * 4));
    v.x *= w; v.y *= w; v.z *= w; v.w *= w;
    float* dp = out + (long long)d * F + c * 4;
    asm volatile("red.global.add.v4.f32 [%0], {%1, %2, %3, %4};"
                 :: "l"(dp), "f"(v.x), "f"(v.y), "f"(v.z), "f"(v.w) : "memory");
}

extern "C" void kernel_launch(void* const* d_in, const int* in_sizes, int n_in,
                              void* d_out, int out_size)
{
    const float* x  = (const float*)d_in[0];
    const float* ew = (const float*)d_in[1];
    const int*   ei = (const int*)d_in[2];
    float* out = (float*)d_out;

    int E = in_sizes[2] / 2;

    cudaMemsetAsync(out, 0, (size_t)out_size * sizeof(float), 0);

    int pairs = E >> 1;
    int total = pairs * 16;
    int blocks = (total + THREADS - 1) / THREADS;
    mp_scatter_kernel<<<blocks, THREADS>>>(x, ew, ei, out, E);

    if (E & 1) {
        int n = 16;
        mp_scatter_tail<<<(n + THREADS - 1) / THREADS, THREADS>>>(x, ew, ei, out, E, E - 1);
    }
}